// round 8
// baseline (speedup 1.0000x reference)
#include <cuda_runtime.h>
#include <math.h>

#define BB 512
#define LL 196
#define CC 64
#define C2 128
#define CHN 128
#define NEC 512
#define NXC 15

// ---- output layout (flattened tuple order) ----
#define REC_N    (BB*CHN*LL)
#define PRED_OFF (REC_N)
#define LOSS_OFF (REC_N + BB*LL)
#define Q_OFF    (LOSS_OFF + 3)

#define VTHR 416        // vq: 13 warps; slot = tid>>3 (52 slots), cg = tid&7
#define NTHR 416        // proj threads

// ---- scratch ----
__device__ float  g_q4[BB*LL*CC];
__device__ float  g_E5T[NXC*NEC*CC];
__device__ float  g_EHT[4*NXC*NEC*C2];
__device__ float  g_e2_5[NXC*NEC];
__device__ float  g_e2_h[4*NXC*NEC];
__device__ double g_acc[6];

// packed f32x2 fma: bit-identical to two scalar __fmaf_rn
__device__ __forceinline__ void ffma2(unsigned long long& acc,
                                      unsigned long long a,
                                      unsigned long long b) {
    asm("fma.rn.f32x2 %0, %1, %2, %0;" : "+l"(acc) : "l"(a), "l"(b));
}
__device__ __forceinline__ unsigned long long pack2(float x) {
    unsigned long long r;
    asm("mov.b64 %0, {%1, %1};" : "=l"(r) : "r"(__float_as_uint(x)));
    return r;
}
__device__ __forceinline__ float lo32(unsigned long long v) {
    return __uint_as_float((unsigned)v);
}
__device__ __forceinline__ float hi32(unsigned long long v) {
    return __uint_as_float((unsigned)(v >> 32));
}

// [D][N] -> [N][D] transpose per codebook; which 0 -> g_E5T, 1 -> g_EHT
// (also zeroes g_acc from its first block)
__global__ void transpose_k(const float* __restrict__ src, int D, int N, int which) {
    __shared__ float tile[32][33];
    if (which == 0 && blockIdx.x == 0 && blockIdx.y == 0 && blockIdx.z == 0 &&
        threadIdx.y == 0 && threadIdx.x < 6)
        g_acc[threadIdx.x] = 0.0;
    float* dstbase = which ? g_EHT : g_E5T;
    const float* s = src + (size_t)blockIdx.z * D * N;
    float* d = dstbase + (size_t)blockIdx.z * D * N;
    int n0 = blockIdx.x * 32, d0 = blockIdx.y * 32;
    for (int ty = threadIdx.y; ty < 32; ty += 8)
        tile[ty][threadIdx.x] = s[(size_t)(d0 + ty) * N + n0 + threadIdx.x];
    __syncthreads();
    for (int ty = threadIdx.y; ty < 32; ty += 8)
        d[(size_t)(n0 + ty) * D + d0 + threadIdx.x] = tile[threadIdx.x][ty];
}

// e2 for BOTH tables in one launch. XLA column-reduce style (bit-identical).
__global__ void e2_all_k() {
    int n = blockIdx.x * (blockDim.x >> 5) + (threadIdx.x >> 5);
    int lane = threadIdx.x & 31;
    const int T5 = NXC * NEC;
    const int TH = 4 * NXC * NEC;
    if (n >= T5 + TH) return;
    const float* row;
    float* dst;
    int D;
    if (n < T5) { row = g_E5T + (size_t)n * CC;        dst = g_e2_5 + n;        D = CC; }
    else        { row = g_EHT + (size_t)(n - T5) * C2; dst = g_e2_h + (n - T5); D = C2; }
    float p = 0.f;
    for (int j = lane; j < D; j += 32)
        p = __fadd_rn(p, __fmul_rn(row[j], row[j]));
    #pragma unroll
    for (int o = 16; o; o >>= 1)
        p = __fadd_rn(p, __shfl_down_sync(0xffffffffu, p, o));
    if (lane == 0) *dst = p;
}

template<int NW>
__device__ __forceinline__ float block_reduceNW(float v, float* red) {
    #pragma unroll
    for (int o = 16; o; o >>= 1) v += __shfl_down_sync(0xffffffffu, v, o);
    int w = threadIdx.x >> 5;
    if ((threadIdx.x & 31) == 0) red[w] = v;
    __syncthreads();
    float s = 0.f;
    if (threadIdx.x == 0) {
        #pragma unroll
        for (int i = 0; i < NW; ++i) s += red[i];
    }
    return s;
}

// ---- VQ: one block per (b [, level]), 196 rows x 512 codes.
// 416 threads: slot = tid>>3 (52 row-groups of 4 rows, 49 real), cg = tid&7
// (8 code-groups of 8 codes). Per k per thread: 1 LDS.128 (4 rows, packed
// pairs) + 4 LDS.128 (permuted duplicated E, 128B-contiguous per warp)
// + 16 FFMA2. Zero pack movs; 5.8% clamped-slot waste.
template<int KD, bool HI, int MAXB>
__global__ __launch_bounds__(VTHR, MAXB)
void vq_kernel(const float* __restrict__ enc,
               const float* __restrict__ Ebase,
               const int*   __restrict__ label,
               float*       __restrict__ qout_hi)
{
    extern __shared__ float sm[];
    float* Xst = sm;                                   // KD*196, [d][l]
    float* x2s = Xst + KD * LL;                        // 196
    unsigned long long* Es2 =
        (unsigned long long*)(x2s + LL);               // KD*64 u64, permuted dup
    float* e2s = (float*)(Es2 + KD * 64);              // 64 (natural order)
    float* bv2 = e2s + 64;                             // 8*196
    int*   bn2 = (int*)(bv2 + 8 * LL);                 // 8*196
    int*   bestn = bn2 + 8 * LL;                       // 196
    float* red = (float*)(bestn + LL);                 // 16

    const int b = blockIdx.x;
    const int lev = HI ? blockIdx.y : 0;
    const int cb = label[b];
    const int tid = threadIdx.x;
    const int slot = tid >> 3;                         // 0..51
    const int cg   = tid & 7;                          // 0..7
    const bool actv = slot < 49;
    const int sc = actv ? slot : 48;                   // clamped row-group

    const float* X  = HI ? (enc + (size_t)(3 - lev) * (BB * LL * CC)) : enc;
    const float* Eg = Ebase + ((size_t)(HI ? lev * NXC : 0) + cb) * ((size_t)KD * NEC);
    const float* ET = (HI ? g_EHT : g_E5T) + ((size_t)(HI ? lev * NXC : 0) + cb) * ((size_t)NEC * KD);
    const float* e2 = (HI ? g_e2_h : g_e2_5) + ((size_t)(HI ? lev * NXC : 0) + cb) * NEC;
    float* qout = HI ? (qout_hi + (size_t)lev * (BB * LL * C2)) : g_q4;
    double* acc = g_acc + (HI ? 1 + lev : 0);

    // stage X transposed: Xst[d][l], l contiguous (row stride 196*4 = 784B | 16)
    for (int idx = tid; idx < LL * KD; idx += VTHR) {
        int ll = idx / KD, d = idx % KD;
        float v;
        if (HI) v = (d < CC) ? X[((size_t)b * LL + ll) * CC + d]
                             : g_q4[((size_t)b * LL + ll) * CC + (d - CC)];
        else    v = X[((size_t)b * LL + ll) * CC + d];
        Xst[d * LL + ll] = v;
    }
    __syncthreads();

    // x2 per row — XLA row-reduce (lane-strided unfused + shfl tree), 13 warps
    {
        const int warp = tid >> 5, lane = tid & 31;
        for (int r = warp; r < LL; r += 13) {
            float p = 0.f;
            #pragma unroll
            for (int j = 0; j < KD / 32; ++j) {
                float xv = Xst[(lane + 32 * j) * LL + r];
                p = __fadd_rn(p, __fmul_rn(xv, xv));
            }
            #pragma unroll
            for (int o = 16; o; o >>= 1)
                p = __fadd_rn(p, __shfl_down_sync(0xffffffffu, p, o));
            if (lane == 0) x2s[r] = p;
        }
    }
    __syncthreads();

    const float x2r0 = x2s[4 * sc + 0];
    const float x2r1 = x2s[4 * sc + 1];
    const float x2r2 = x2s[4 * sc + 2];
    const float x2r3 = x2s[4 * sc + 3];
    float best0 = 3.402823466e38f, best1 = best0, best2 = best0, best3 = best0;
    int bi0 = 0x7fffffff, bi1 = bi0, bi2 = bi0, bi3 = bi0;

    for (int t = 0; t < NEC / 64; ++t) {
        __syncthreads();
        // stage E tile, duplicated + permuted: code c -> u64 slot (j*8+cgc)*2+h,
        // where cgc = c>>3, w = c&7, j = w>>1, h = w&1.
        for (int i = tid; i < KD * 64; i += VTHR) {
            int k = i >> 6, c = i & 63;
            int cgc = c >> 3, w = c & 7;
            int pos = (((w >> 1) << 3) + cgc) * 2 + (w & 1);
            float e = Eg[(size_t)k * NEC + t * 64 + c];
            ((float2*)Es2)[k * 64 + pos] = make_float2(e, e);
        }
        if (tid < 64) e2s[tid] = e2[t * 64 + tid];
        __syncthreads();

        unsigned long long a0[8], a1[8];
        #pragma unroll
        for (int c = 0; c < 8; ++c) { a0[c] = 0ull; a1[c] = 0ull; }

        #pragma unroll 2
        for (int k = 0; k < KD; ++k) {
            // rows 4sc..4sc+3 as two packed pairs (byte addr: k*784 + sc*16)
            ulonglong2 xv = *(const ulonglong2*)(Xst + k * LL + 4 * sc);
            const ulonglong2* ep = (const ulonglong2*)(Es2 + k * 64);
            #pragma unroll
            for (int j = 0; j < 4; ++j) {
                ulonglong2 e = ep[j * 8 + cg];   // codes (cg*8+2j, cg*8+2j+1), dup
                ffma2(a0[2 * j],     xv.x, e.x);
                ffma2(a0[2 * j + 1], xv.x, e.y);
                ffma2(a1[2 * j],     xv.y, e.x);
                ffma2(a1[2 * j + 1], xv.y, e.y);
            }
        }

        #pragma unroll
        for (int c = 0; c < 8; ++c) {
            float e2v = e2s[cg * 8 + c];
            int n = t * 64 + cg * 8 + c;
            float v0 = __fadd_rn(__fsub_rn(x2r0, __fmul_rn(2.f, lo32(a0[c]))), e2v);
            float v1 = __fadd_rn(__fsub_rn(x2r1, __fmul_rn(2.f, hi32(a0[c]))), e2v);
            float v2 = __fadd_rn(__fsub_rn(x2r2, __fmul_rn(2.f, lo32(a1[c]))), e2v);
            float v3 = __fadd_rn(__fsub_rn(x2r3, __fmul_rn(2.f, hi32(a1[c]))), e2v);
            if (v0 < best0) { best0 = v0; bi0 = n; }
            if (v1 < best1) { best1 = v1; bi1 = n; }
            if (v2 < best2) { best2 = v2; bi2 = n; }
            if (v3 < best3) { best3 = v3; bi3 = n; }
        }
    }

    if (actv) {
        int rb = 4 * slot;
        bv2[cg * LL + rb + 0] = best0; bn2[cg * LL + rb + 0] = bi0;
        bv2[cg * LL + rb + 1] = best1; bn2[cg * LL + rb + 1] = bi1;
        bv2[cg * LL + rb + 2] = best2; bn2[cg * LL + rb + 2] = bi2;
        bv2[cg * LL + rb + 3] = best3; bn2[cg * LL + rb + 3] = bi3;
    }
    __syncthreads();

    // combine 8 code-groups per row: lexicographic (value, index) min = first-min
    if (tid < LL) {
        float v = bv2[tid]; int n = bn2[tid];
        #pragma unroll
        for (int q = 1; q < 8; ++q) {
            float vq = bv2[q * LL + tid]; int nq = bn2[q * LL + tid];
            if (vq < v || (vq == v && nq < n)) { v = vq; n = nq; }
        }
        bestn[tid] = n;
    }
    __syncthreads();

    // gather codes, straight-through q, diff
    float lsum = 0.f;
    for (int idx = tid; idx < LL * KD; idx += VTHR) {
        int ll = idx / KD, d = idx % KD;
        float c  = ET[(size_t)bestn[ll] * KD + d];
        float xv = Xst[d * LL + ll];
        float df = __fsub_rn(c, xv);
        lsum = __fmaf_rn(df, df, lsum);
        qout[((size_t)b * LL + ll) * KD + d] = __fadd_rn(xv, df);
    }
    float bs = block_reduceNW<13>(lsum, red);
    if (tid == 0) atomicAdd(acc, (double)bs);
}

// ---- projection + pred + feature loss (unchanged from R6) ----
__global__ __launch_bounds__(NTHR, 1)
void proj_kernel(const float* __restrict__ dec,
                 const float* __restrict__ org,
                 const float* __restrict__ W,
                 const float* __restrict__ bvec,
                 const int*   __restrict__ label,
                 float*       __restrict__ rec_out,
                 float*       __restrict__ pred_out)
{
    constexpr int PL = 197;
    extern __shared__ float sm[];
    float* Dst = sm;                // 128*PL
    float* ps  = Dst + 128 * PL;    // 208
    float* Ws  = ps + 208;          // 128*64
    float* red = Ws + 128 * 64;     // 13

    const int b = blockIdx.x, tid = threadIdx.x;
    const int cb = label[b];
    const int half = (tid >= 208) ? 1 : 0;
    const int l = tid - 208 * half;

    for (int idx = tid; idx < LL * CHN; idx += NTHR) {
        int ll = idx >> 7, d = idx & 127;
        Dst[d * PL + ll] = dec[((size_t)ll * BB + b) * CHN + d];
    }
    const float* Wcb = W + (size_t)cb * CHN * CHN;
    const float* bcb = bvec + cb * CHN;
    float psum = 0.f;

    for (int t = 0; t < 2; ++t) {
        __syncthreads();
        for (int i = tid; i < 128 * 16; i += NTHR) {
            int k = i >> 4, j = i & 15;
            ((float4*)Ws)[k * 16 + j] = *(const float4*)(Wcb + (size_t)k * CHN + t * 64 + j * 4);
        }
        __syncthreads();
        if (l < LL) {
            unsigned long long a2[16];
            #pragma unroll
            for (int j = 0; j < 16; ++j) a2[j] = 0ull;
            #pragma unroll 2
            for (int k = 0; k < 128; ++k) {
                unsigned long long xx = pack2(Dst[k * PL + l]);
                const ulonglong2* er = (const ulonglong2*)(Ws + k * 64 + half * 32);
                #pragma unroll
                for (int j = 0; j < 8; ++j) {
                    ulonglong2 e = er[j];
                    ffma2(a2[2 * j], xx, e.x);
                    ffma2(a2[2 * j + 1], xx, e.y);
                }
            }
            #pragma unroll
            for (int j = 0; j < 16; ++j) {
                #pragma unroll
                for (int ss = 0; ss < 2; ++ss) {
                    float av = __uint_as_float((unsigned)(a2[j] >> (32 * ss)));
                    int o = t * 64 + half * 32 + 2 * j + ss;
                    float r = __fadd_rn(av, bcb[o]);
                    float g = org[(size_t)b * CHN * LL + (size_t)o * LL + l];
                    float e = __fsub_rn(r, g);
                    psum = __fmaf_rn(e, e, psum);
                    rec_out[(size_t)b * CHN * LL + (size_t)o * LL + l] = r;
                }
            }
        }
    }
    __syncthreads();
    if (half == 1 && l < LL) ps[l] = psum;
    __syncthreads();
    if (half == 0 && l < LL)
        pred_out[(size_t)b * LL + l] = __fsqrt_rn(__fadd_rn(psum, ps[l]));
    float bs = block_reduceNW<13>(psum, red);
    if (tid == 0) atomicAdd(&g_acc[5], (double)bs);
}

__global__ void final_k(float* __restrict__ out) {
    if (threadIdx.x == 0 && blockIdx.x == 0) {
        double latent = g_acc[0] / ((double)BB * LL * CC)
                      + (g_acc[1] + g_acc[2] + g_acc[3] + g_acc[4]) / ((double)BB * LL * C2);
        double feat = g_acc[5] / ((double)BB * CHN * LL);
        out[LOSS_OFF + 0] = (float)(0.25 * latent + feat);
        out[LOSS_OFF + 1] = (float)feat;
        out[LOSS_OFF + 2] = (float)latent;
    }
}

extern "C" void kernel_launch(void* const* d_in, const int* in_sizes, int n_in,
                              void* d_out, int out_size) {
    const float* enc      = (const float*)d_in[0];
    const float* dec      = (const float*)d_in[1];
    const float* org      = (const float*)d_in[2];
    const float* embed5   = (const float*)d_in[3];
    const float* embed_hi = (const float*)d_in[4];
    const float* W        = (const float*)d_in[5];
    const float* bvec     = (const float*)d_in[6];
    const int*   label    = (const int*)d_in[7];
    float* out = (float*)d_out;

    // floats: Xst(KD*196)+x2s(196)+Es2(KD*128)+e2s(64)+bv2(1568)+bn2(1568)+bestn(196)+red(16)
    const size_t sm64  = (size_t)(64  * LL + LL + 64  * 128 + 64 + 8 * LL * 2 + LL + 16) * 4;
    const size_t sm128 = (size_t)(128 * LL + LL + 128 * 128 + 64 + 8 * LL * 2 + LL + 16) * 4;
    const size_t smP   = (size_t)(128 * 197 + 208 + 128 * 64 + 13 + 16) * 4;

    cudaFuncSetAttribute(vq_kernel<64, false, 2>, cudaFuncAttributeMaxDynamicSharedMemorySize, (int)sm64);
    cudaFuncSetAttribute(vq_kernel<128, true, 1>, cudaFuncAttributeMaxDynamicSharedMemorySize, (int)sm128);
    cudaFuncSetAttribute(proj_kernel, cudaFuncAttributeMaxDynamicSharedMemorySize, (int)smP);

    // launch order: profiled slot = 0-based launch 3 = vq5
    transpose_k<<<dim3(16, 2, 15), dim3(32, 8)>>>(embed5,   64,  512, 0);   // 0 (zeroes g_acc)
    transpose_k<<<dim3(16, 4, 60), dim3(32, 8)>>>(embed_hi, 128, 512, 1);   // 1
    e2_all_k<<<(75 * 512 + 7) / 8, 256>>>();                                // 2

    vq_kernel<64, false, 2><<<512, VTHR, sm64>>>(                           // 3 <- profiled
        enc + (size_t)4 * BB * LL * CC, embed5, label, nullptr);
    vq_kernel<128, true, 1><<<dim3(512, 4), VTHR, sm128>>>(                 // 4
        enc, embed_hi, label, out + Q_OFF);

    proj_kernel<<<512, NTHR, smP>>>(dec, org, W, bvec, label, out, out + PRED_OFF);  // 5

    final_k<<<1, 1>>>(out);                                                 // 6
}

// round 11
// speedup vs baseline: 1.4444x; 1.4444x over previous
#include <cuda_runtime.h>
#include <math.h>

#define BB 512
#define LL 196
#define CC 64
#define C2 128
#define CHN 128
#define NEC 512
#define NXC 15

// ---- output layout (flattened tuple order) ----
#define REC_N    (BB*CHN*LL)
#define PRED_OFF (REC_N)
#define LOSS_OFF (REC_N + BB*LL)
#define Q_OFF    (LOSS_OFF + 3)

#define NTHR 416        // 13 warps
#define QSLOT 104       // row slots per code-quarter (4*104 = 416)

// ---- scratch ----
__device__ float  g_q4[BB*LL*CC];
__device__ float  g_E5T[NXC*NEC*CC];
__device__ float  g_EHT[4*NXC*NEC*C2];
__device__ float  g_e2_5[NXC*NEC];
__device__ float  g_e2_h[4*NXC*NEC];
__device__ double g_acc[6];

// packed f32x2 fma: bit-identical to two scalar __fmaf_rn
__device__ __forceinline__ void ffma2(unsigned long long& acc,
                                      unsigned long long a,
                                      unsigned long long b) {
    asm("fma.rn.f32x2 %0, %1, %2, %0;" : "+l"(acc) : "l"(a), "l"(b));
}
__device__ __forceinline__ unsigned long long pack2(float x) {
    unsigned long long r;
    asm("mov.b64 %0, {%1, %1};" : "=l"(r) : "r"(__float_as_uint(x)));
    return r;
}

// [D][N] -> [N][D] transpose per codebook; which 0 -> g_E5T, 1 -> g_EHT
// (also zeroes g_acc from its first block)
__global__ void transpose_k(const float* __restrict__ src, int D, int N, int which) {
    __shared__ float tile[32][33];
    if (which == 0 && blockIdx.x == 0 && blockIdx.y == 0 && blockIdx.z == 0 &&
        threadIdx.y == 0 && threadIdx.x < 6)
        g_acc[threadIdx.x] = 0.0;
    float* dstbase = which ? g_EHT : g_E5T;
    const float* s = src + (size_t)blockIdx.z * D * N;
    float* d = dstbase + (size_t)blockIdx.z * D * N;
    int n0 = blockIdx.x * 32, d0 = blockIdx.y * 32;
    for (int ty = threadIdx.y; ty < 32; ty += 8)
        tile[ty][threadIdx.x] = s[(size_t)(d0 + ty) * N + n0 + threadIdx.x];
    __syncthreads();
    for (int ty = threadIdx.y; ty < 32; ty += 8)
        d[(size_t)(n0 + ty) * D + d0 + threadIdx.x] = tile[threadIdx.x][ty];
}

// e2 for BOTH tables in one launch. XLA column-reduce style (bit-identical).
__global__ void e2_all_k() {
    int n = blockIdx.x * (blockDim.x >> 5) + (threadIdx.x >> 5);
    int lane = threadIdx.x & 31;
    const int T5 = NXC * NEC;
    const int TH = 4 * NXC * NEC;
    if (n >= T5 + TH) return;
    const float* row;
    float* dst;
    int D;
    if (n < T5) { row = g_E5T + (size_t)n * CC;        dst = g_e2_5 + n;        D = CC; }
    else        { row = g_EHT + (size_t)(n - T5) * C2; dst = g_e2_h + (n - T5); D = C2; }
    float p = 0.f;
    for (int j = lane; j < D; j += 32)
        p = __fadd_rn(p, __fmul_rn(row[j], row[j]));
    #pragma unroll
    for (int o = 16; o; o >>= 1)
        p = __fadd_rn(p, __shfl_down_sync(0xffffffffu, p, o));
    if (lane == 0) *dst = p;
}

template<int NW>
__device__ __forceinline__ float block_reduceNW(float v, float* red) {
    #pragma unroll
    for (int o = 16; o; o >>= 1) v += __shfl_down_sync(0xffffffffu, v, o);
    int w = threadIdx.x >> 5;
    if ((threadIdx.x & 31) == 0) red[w] = v;
    __syncthreads();
    float s = 0.f;
    if (threadIdx.x == 0) {
        #pragma unroll
        for (int i = 0; i < NW; ++i) s += red[i];
    }
    return s;
}

// ---- VQ (R6 structure): one block per (b [, level]), full 196 rows;
// 416 threads = 4 code-quarters (16 codes) x 104 row slots; each slot owns
// rows slot and slot+104. DB=true double-buffers the E tile (LDG into regs
// before the FFMA2 block, STS after) — staging-only change, numerics identical.
template<int KD, bool HI, int MAXB, bool DB>
__global__ __launch_bounds__(NTHR, MAXB)
void vq_kernel(const float* __restrict__ enc,
               const float* __restrict__ Ebase,
               const int*   __restrict__ label,
               float*       __restrict__ qout_hi)
{
    constexpr int PL = 197;                   // 197 mod 32 = 5 -> conflict-free
    constexpr int NBUF = DB ? 2 : 1;
    extern __shared__ float sm[];
    float* Xst = sm;                          // KD*PL
    float* x2s = Xst + KD * PL;               // 196
    float* Es  = x2s + 196;                   // KD*64*NBUF (16B aligned offset)
    float* e2a = Es + KD * 64 * NBUF;         // 512 (all e2, preloaded)
    float* bv  = e2a + 512;                   // 2*416
    int*   bn  = (int*)(bv + 2 * NTHR);       // 2*416
    int*   bestn = bn + 2 * NTHR;             // 196
    float* red = (float*)(bestn + LL);        // 13

    const int b = blockIdx.x;
    const int lev = HI ? blockIdx.y : 0;
    const int cb = label[b];
    const int tid = threadIdx.x;
    const int qtr = tid / QSLOT;
    const int slot = tid - qtr * QSLOT;       // row A = slot
    const bool hasB = (slot < LL - QSLOT);    // row B = slot + 104 (92 valid)
    const int rowB = hasB ? slot + QSLOT : slot;

    const float* X  = HI ? (enc + (size_t)(3 - lev) * (BB * LL * CC)) : enc;
    const float* Eg = Ebase + ((size_t)(HI ? lev * NXC : 0) + cb) * ((size_t)KD * NEC);
    const float* ET = (HI ? g_EHT : g_E5T) + ((size_t)(HI ? lev * NXC : 0) + cb) * ((size_t)NEC * KD);
    const float* e2 = (HI ? g_e2_h : g_e2_5) + ((size_t)(HI ? lev * NXC : 0) + cb) * NEC;
    float* qout = HI ? (qout_hi + (size_t)lev * (BB * LL * C2)) : g_q4;
    double* acc = g_acc + (HI ? 1 + lev : 0);

    // stage X transposed: Xst[d][l]
    for (int idx = tid; idx < LL * KD; idx += NTHR) {
        int ll = idx / KD, d = idx % KD;
        float v;
        if (HI) v = (d < CC) ? X[((size_t)b * LL + ll) * CC + d]
                             : g_q4[((size_t)b * LL + ll) * CC + (d - CC)];
        else    v = X[((size_t)b * LL + ll) * CC + d];
        Xst[d * PL + ll] = v;
    }
    // preload ALL e2 (same values as before -> bit-identical dists)
    for (int i = tid; i < NEC; i += NTHR) e2a[i] = e2[i];
    __syncthreads();

    // x2 per row — XLA row-reduce (lane-strided unfused + shfl tree)
    {
        const int warp = tid >> 5, lane = tid & 31;
        for (int r = warp; r < LL; r += 13) {
            float p = 0.f;
            #pragma unroll
            for (int j = 0; j < KD / 32; ++j) {
                float xv = Xst[(lane + 32 * j) * PL + r];
                p = __fadd_rn(p, __fmul_rn(xv, xv));
            }
            #pragma unroll
            for (int o = 16; o; o >>= 1)
                p = __fadd_rn(p, __shfl_down_sync(0xffffffffu, p, o));
            if (lane == 0) x2s[r] = p;
        }
    }

    if (DB) {
        // prologue: stage tile 0 into buffer 0
        for (int i = tid; i < KD * 16; i += NTHR)
            ((float4*)Es)[i] = *(const float4*)(Eg + (size_t)(i >> 4) * NEC + (i & 15) * 4);
    }
    __syncthreads();

    const float x2A = x2s[slot];
    const float x2B = x2s[rowB];
    float bestA = 3.402823466e38f, bestB = 3.402823466e38f;
    int biA = 0x7fffffff, biB = 0x7fffffff;

    for (int t = 0; t < NEC / 64; ++t) {
        const float* curEs;
        float4 nx[5];
        if (DB) {
            curEs = Es + (t & 1) * (KD * 64);
            if (t < 7) {
                int nc = 0;
                for (int i = tid; i < KD * 16; i += NTHR)
                    nx[nc++] = *(const float4*)(Eg + (size_t)(i >> 4) * NEC + (t + 1) * 64 + (i & 15) * 4);
            }
        } else {
            curEs = Es;
            __syncthreads();
            for (int i = tid; i < KD * 16; i += NTHR) {
                int k = i >> 4, j = i & 15;
                ((float4*)Es)[k * 16 + j] = *(const float4*)(Eg + (size_t)k * NEC + t * 64 + j * 4);
            }
            __syncthreads();
        }

        {
            unsigned long long aA[8], aB[8];
            #pragma unroll
            for (int m = 0; m < 8; ++m) { aA[m] = 0ull; aB[m] = 0ull; }
            #pragma unroll 4
            for (int k = 0; k < KD; ++k) {
                unsigned long long xxA = pack2(Xst[k * PL + slot]);
                unsigned long long xxB = pack2(Xst[k * PL + rowB]);
                const ulonglong2* er = (const ulonglong2*)(curEs + k * 64 + qtr * 16);
                #pragma unroll
                for (int j = 0; j < 4; ++j) {
                    ulonglong2 e = er[j];
                    ffma2(aA[2 * j],     xxA, e.x);
                    ffma2(aA[2 * j + 1], xxA, e.y);
                    ffma2(aB[2 * j],     xxB, e.x);
                    ffma2(aB[2 * j + 1], xxB, e.y);
                }
            }
            #pragma unroll
            for (int m = 0; m < 8; ++m) {
                float eA0 = e2a[t * 64 + qtr * 16 + 2 * m];
                float eA1 = e2a[t * 64 + qtr * 16 + 2 * m + 1];
                int n0 = t * 64 + qtr * 16 + 2 * m;
                float dA0 = __fadd_rn(__fsub_rn(x2A, __fmul_rn(2.f, __uint_as_float((unsigned)aA[m]))), eA0);
                float dA1 = __fadd_rn(__fsub_rn(x2A, __fmul_rn(2.f, __uint_as_float((unsigned)(aA[m] >> 32)))), eA1);
                float dB0 = __fadd_rn(__fsub_rn(x2B, __fmul_rn(2.f, __uint_as_float((unsigned)aB[m]))), eA0);
                float dB1 = __fadd_rn(__fsub_rn(x2B, __fmul_rn(2.f, __uint_as_float((unsigned)(aB[m] >> 32)))), eA1);
                if (dA0 < bestA) { bestA = dA0; biA = n0; }
                if (dA1 < bestA) { bestA = dA1; biA = n0 + 1; }
                if (dB0 < bestB) { bestB = dB0; biB = n0; }
                if (dB1 < bestB) { bestB = dB1; biB = n0 + 1; }
            }
        }

        if (DB) {
            if (t < 7) {
                float4* nxt = (float4*)Es + ((t + 1) & 1) * (KD * 16);
                int nc = 0;
                for (int i = tid; i < KD * 16; i += NTHR) nxt[i] = nx[nc++];
            }
            __syncthreads();
        }
    }
    bv[tid] = bestA; bn[tid] = biA;
    bv[NTHR + tid] = bestB; bn[NTHR + tid] = biB;   // only slots<92 entries are read
    __syncthreads();

    // combine 4 quarters per row: global first-min (smallest index among equal minima)
    if (tid < LL) {
        int base = (tid < QSLOT) ? tid : (NTHR + tid - QSLOT);
        float v = bv[base]; int n = bn[base];
        #pragma unroll
        for (int q = 1; q < 4; ++q) {
            float vq = bv[base + q * QSLOT]; int nq = bn[base + q * QSLOT];
            if (vq < v || (vq == v && nq < n)) { v = vq; n = nq; }
        }
        bestn[tid] = n;
    }
    __syncthreads();

    // gather codes, straight-through q, diff
    float lsum = 0.f;
    for (int idx = tid; idx < LL * KD; idx += NTHR) {
        int ll = idx / KD, d = idx % KD;
        float c  = ET[(size_t)bestn[ll] * KD + d];
        float xv = Xst[d * PL + ll];
        float df = __fsub_rn(c, xv);
        lsum = __fmaf_rn(df, df, lsum);
        qout[((size_t)b * LL + ll) * KD + d] = __fadd_rn(xv, df);
    }
    float bs = block_reduceNW<13>(lsum, red);
    if (tid == 0) atomicAdd(acc, (double)bs);
}

// ---- projection + pred + feature loss (unchanged passing version) ----
__global__ __launch_bounds__(NTHR, 1)
void proj_kernel(const float* __restrict__ dec,
                 const float* __restrict__ org,
                 const float* __restrict__ W,
                 const float* __restrict__ bvec,
                 const int*   __restrict__ label,
                 float*       __restrict__ rec_out,
                 float*       __restrict__ pred_out)
{
    constexpr int PL = 197;
    extern __shared__ float sm[];
    float* Dst = sm;                // 128*PL
    float* ps  = Dst + 128 * PL;    // 208
    float* Ws  = ps + 208;          // 128*64
    float* red = Ws + 128 * 64;     // 13

    const int b = blockIdx.x, tid = threadIdx.x;
    const int cb = label[b];
    const int half = (tid >= 208) ? 1 : 0;
    const int l = tid - 208 * half;

    for (int idx = tid; idx < LL * CHN; idx += NTHR) {
        int ll = idx >> 7, d = idx & 127;
        Dst[d * PL + ll] = dec[((size_t)ll * BB + b) * CHN + d];
    }
    const float* Wcb = W + (size_t)cb * CHN * CHN;
    const float* bcb = bvec + cb * CHN;
    float psum = 0.f;

    for (int t = 0; t < 2; ++t) {
        __syncthreads();
        for (int i = tid; i < 128 * 16; i += NTHR) {
            int k = i >> 4, j = i & 15;
            ((float4*)Ws)[k * 16 + j] = *(const float4*)(Wcb + (size_t)k * CHN + t * 64 + j * 4);
        }
        __syncthreads();
        if (l < LL) {
            unsigned long long a2[16];
            #pragma unroll
            for (int j = 0; j < 16; ++j) a2[j] = 0ull;
            #pragma unroll 2
            for (int k = 0; k < 128; ++k) {
                unsigned long long xx = pack2(Dst[k * PL + l]);
                const ulonglong2* er = (const ulonglong2*)(Ws + k * 64 + half * 32);
                #pragma unroll
                for (int j = 0; j < 8; ++j) {
                    ulonglong2 e = er[j];
                    ffma2(a2[2 * j], xx, e.x);
                    ffma2(a2[2 * j + 1], xx, e.y);
                }
            }
            #pragma unroll
            for (int j = 0; j < 16; ++j) {
                #pragma unroll
                for (int ss = 0; ss < 2; ++ss) {
                    float av = __uint_as_float((unsigned)(a2[j] >> (32 * ss)));
                    int o = t * 64 + half * 32 + 2 * j + ss;
                    float r = __fadd_rn(av, bcb[o]);
                    float g = org[(size_t)b * CHN * LL + (size_t)o * LL + l];
                    float e = __fsub_rn(r, g);
                    psum = __fmaf_rn(e, e, psum);
                    rec_out[(size_t)b * CHN * LL + (size_t)o * LL + l] = r;
                }
            }
        }
    }
    __syncthreads();
    if (half == 1 && l < LL) ps[l] = psum;
    __syncthreads();
    if (half == 0 && l < LL)
        pred_out[(size_t)b * LL + l] = __fsqrt_rn(__fadd_rn(psum, ps[l]));
    float bs = block_reduceNW<13>(psum, red);
    if (tid == 0) atomicAdd(&g_acc[5], (double)bs);
}

__global__ void final_k(float* __restrict__ out) {
    if (threadIdx.x == 0 && blockIdx.x == 0) {
        double latent = g_acc[0] / ((double)BB * LL * CC)
                      + (g_acc[1] + g_acc[2] + g_acc[3] + g_acc[4]) / ((double)BB * LL * C2);
        double feat = g_acc[5] / ((double)BB * CHN * LL);
        out[LOSS_OFF + 0] = (float)(0.25 * latent + feat);
        out[LOSS_OFF + 1] = (float)feat;
        out[LOSS_OFF + 2] = (float)latent;
    }
}

extern "C" void kernel_launch(void* const* d_in, const int* in_sizes, int n_in,
                              void* d_out, int out_size) {
    const float* enc      = (const float*)d_in[0];
    const float* dec      = (const float*)d_in[1];
    const float* org      = (const float*)d_in[2];
    const float* embed5   = (const float*)d_in[3];
    const float* embed_hi = (const float*)d_in[4];
    const float* W        = (const float*)d_in[5];
    const float* bvec     = (const float*)d_in[6];
    const int*   label    = (const int*)d_in[7];
    float* out = (float*)d_out;

    // floats: Xst(KD*197)+x2s(196)+Es(KD*64*NBUF)+e2a(512)+bv(832)+bn(832)+bestn(196)+red(13)+pad
    const size_t sm64  = (size_t)(64  * 197 + 196 + 64  * 64 * 1 + 512 + 2 * NTHR + 2 * NTHR + LL + 13 + 16) * 4;
    const size_t sm128 = (size_t)(128 * 197 + 196 + 128 * 64 * 2 + 512 + 2 * NTHR + 2 * NTHR + LL + 13 + 16) * 4;
    const size_t smP   = (size_t)(128 * 197 + 208 + 128 * 64 + 13 + 16) * 4;

    cudaFuncSetAttribute((const void*)vq_kernel<64, false, 2, false>,
                         cudaFuncAttributeMaxDynamicSharedMemorySize, (int)sm64);
    cudaFuncSetAttribute((const void*)vq_kernel<128, true, 1, true>,
                         cudaFuncAttributeMaxDynamicSharedMemorySize, (int)sm128);
    cudaFuncSetAttribute((const void*)proj_kernel,
                         cudaFuncAttributeMaxDynamicSharedMemorySize, (int)smP);

    // launch order: profiled slot = 0-based launch 3 = vq5
    transpose_k<<<dim3(16, 2, 15), dim3(32, 8)>>>(embed5,   64,  512, 0);   // 0 (zeroes g_acc)
    transpose_k<<<dim3(16, 4, 60), dim3(32, 8)>>>(embed_hi, 128, 512, 1);   // 1
    e2_all_k<<<(75 * 512 + 7) / 8, 256>>>();                                // 2

    vq_kernel<64, false, 2, false><<<512, NTHR, sm64>>>(                    // 3 <- profiled
        enc + (size_t)4 * BB * LL * CC, embed5, label, nullptr);
    vq_kernel<128, true, 1, true><<<dim3(512, 4), NTHR, sm128>>>(           // 4
        enc, embed_hi, label, out + Q_OFF);

    proj_kernel<<<512, NTHR, smP>>>(dec, org, W, bvec, label, out, out + PRED_OFF);  // 5

    final_k<<<1, 1>>>(out);                                                 // 6
}